// round 8
// baseline (speedup 1.0000x reference)
#include <cuda_runtime.h>
#include <math.h>

// Fixed-shape problem: N=16384, D=8, pid in [0,2000), K=128, R=1
#define NMAX    16384
#define NPIDMAX 2048
#define KSEL2   129     // top-(K+1) including self (self weight = 0)
#define CPT     4       // max condensation points per repulsion block
#define RT      256     // threads per block
#define NB      256     // histogram bins over d2 in [0,1]
#define BCAP    128     // boundary-bin candidate capacity per CP
#define NBLK    592     // 148 SMs x 4 blocks: one balanced wave

// -------- device scratch (small, allocation-free) --------
__device__ unsigned long long g_best[NPIDMAX];   // per-pid packed (beta_bits<<32 | ~idx)
__device__ float  g_q[NMAX];
__device__ float  g_n2[NMAX];
__device__ float4 g_xp[NMAX * 2];                // x packed as 2 float4 per node
__device__ int    g_cplist[NPIDMAX];
__device__ int    g_cpcount;
__device__ double g_att;
__device__ double g_rep;
__device__ int    g_maskcnt;

// ---- packed f32x2 helpers ----
__device__ __forceinline__ unsigned long long pk2(float lo, float hi) {
    unsigned long long r;
    asm("mov.b64 %0, {%1, %2};" : "=l"(r) : "f"(lo), "f"(hi));
    return r;
}

// d2 = n2j + n2c - 2*dot(xj, xc), with cs = packed(-2*xc) and n2c2 = pack(n2c, 0)
__device__ __forceinline__ float d2_f32x2(const unsigned long long js[4],
                                          const unsigned long long cs[4],
                                          unsigned long long n2c2, float n2j) {
    unsigned long long acc;
    asm("fma.rn.f32x2 %0, %1, %2, %3;" : "=l"(acc) : "l"(js[0]), "l"(cs[0]), "l"(n2c2));
    asm("fma.rn.f32x2 %0, %1, %2, %3;" : "=l"(acc) : "l"(js[1]), "l"(cs[1]), "l"(acc));
    asm("fma.rn.f32x2 %0, %1, %2, %3;" : "=l"(acc) : "l"(js[2]), "l"(cs[2]), "l"(acc));
    asm("fma.rn.f32x2 %0, %1, %2, %3;" : "=l"(acc) : "l"(js[3]), "l"(cs[3]), "l"(acc));
    float lo, hi;
    asm("mov.b64 {%0, %1}, %2;" : "=f"(lo), "=f"(hi) : "l"(acc));
    return (lo + hi) + n2j;
}

__global__ void k_init() {
    int i = blockIdx.x * blockDim.x + threadIdx.x;
    if (i < NPIDMAX) g_best[i] = 0ULL;
    if (i == 0) { g_cpcount = 0; g_att = 0.0; g_rep = 0.0; g_maskcnt = 0; }
}

// q = arctanh(beta)^2 + 0.01 ; |x|^2 ; pack x ; per-pid best
__global__ void k_bestq(const float* __restrict__ beta, const int* __restrict__ pid,
                        const float* __restrict__ x, int N) {
    int i = blockIdx.x * blockDim.x + threadIdx.x;
    if (i >= N) return;
    float b = beta[i];
    float t = atanhf(b);
    g_q[i] = t * t + 0.01f;
    float4 v0 = *(const float4*)(x + (size_t)i * 8);
    float4 v1 = *(const float4*)(x + (size_t)i * 8 + 4);
    float n2 = v0.x * v0.x + v0.y * v0.y + v0.z * v0.z + v0.w * v0.w
             + v1.x * v1.x + v1.y * v1.y + v1.z * v1.z + v1.w * v1.w;
    g_n2[i] = n2;
    g_xp[2 * i + 0] = v0;
    g_xp[2 * i + 1] = v1;
    int p = pid[i];
    if (p > 0 && p < NPIDMAX) {
        unsigned long long key =
            ((unsigned long long)__float_as_uint(b) << 32) |
            (unsigned long long)(0xFFFFFFFFu - (unsigned)i);
        atomicMax(&g_best[p], key);
    }
}

// compact (threads < NPIDMAX) + attraction, fused
__global__ void k_attract(const float* __restrict__ x, const int* __restrict__ pid,
                          const int* __restrict__ recon, const float* __restrict__ pt,
                          const float* __restrict__ eta, int N) {
    int i = blockIdx.x * blockDim.x + threadIdx.x;
    if (i > 0 && i < NPIDMAX) {
        unsigned long long key = g_best[i];
        if (key != 0ULL) {
            int idx = (int)(0xFFFFFFFFu - (unsigned)(key & 0xFFFFFFFFull));
            int pos = atomicAdd(&g_cpcount, 1);
            g_cplist[pos] = idx;
        }
    }
    float va = 0.0f; int m = 0;
    if (i < N) {
        int p = pid[i];
        if (p > 0 && pt[i] > 0.9f && recon[i] > 0 && fabsf(eta[i]) < 4.0f) {
            unsigned long long key = g_best[p];
            int a = (int)(0xFFFFFFFFu - (unsigned)(key & 0xFFFFFFFFull));
            const float4* xi = (const float4*)(x + (size_t)i * 8);
            const float4* xa = (const float4*)(x + (size_t)a * 8);
            float4 i0 = xi[0], i1 = xi[1], a0 = xa[0], a1 = xa[1];
            float d, d2 = 0.0f;
            d = i0.x - a0.x; d2 += d * d;
            d = i0.y - a0.y; d2 += d * d;
            d = i0.z - a0.z; d2 += d * d;
            d = i0.w - a0.w; d2 += d * d;
            d = i1.x - a1.x; d2 += d * d;
            d = i1.y - a1.y; d2 += d * d;
            d = i1.z - a1.z; d2 += d * d;
            d = i1.w - a1.w; d2 += d * d;
            va = d2 * g_q[i] * g_q[a];
            m = 1;
        }
    }
    #pragma unroll
    for (int o = 16; o; o >>= 1) {
        va += __shfl_down_sync(0xFFFFFFFFu, va, o);
        m  += __shfl_down_sync(0xFFFFFFFFu, m,  o);
    }
    if ((threadIdx.x & 31) == 0 && (m || va != 0.0f)) {
        atomicAdd(&g_att, (double)va);
        atomicAdd(&g_maskcnt, m);
    }
}

// ---- repulsion: pass A = count histogram; pass B = weights below boundary + gather ----
__global__ void __launch_bounds__(RT, 4) k_repulse(const int* __restrict__ pid, int N) {
    __shared__ int      s_hist[CPT][NB];
    __shared__ int      s_Bs[CPT];
    __shared__ int      s_rs[CPT];
    __shared__ int      s_bcnt[CPT];
    __shared__ unsigned s_bk[CPT][BCAP];
    __shared__ float    s_bw[CPT][BCAP];
    __shared__ int      s_pidc[CPT];
    __shared__ float    s_qc[CPT];
    __shared__ float    s_red[RT / 32];

    int tid = threadIdx.x;
    int ncp = g_cpcount;
    // balanced CP ranges across NBLK blocks
    int start = (int)(((long long)ncp * blockIdx.x) / NBLK);
    int end   = (int)(((long long)ncp * (blockIdx.x + 1)) / NBLK);
    int nact  = end - start;
    if (nact <= 0) return;

    // register-resident packed CP data: cs = -2*xc as 4 b64 dim-pairs, n2c2 = pack(n2c, 0)
    unsigned long long cs[CPT][4], n2c2[CPT];
    #pragma unroll
    for (int c = 0; c < CPT; c++) {
        bool act = c < nact;
        int ci = act ? g_cplist[start + c] : 0;
        float4 p0 = g_xp[2 * ci + 0];
        float4 p1 = g_xp[2 * ci + 1];
        cs[c][0] = pk2(-2.0f * p0.x, -2.0f * p0.y);
        cs[c][1] = pk2(-2.0f * p0.z, -2.0f * p0.w);
        cs[c][2] = pk2(-2.0f * p1.x, -2.0f * p1.y);
        cs[c][3] = pk2(-2.0f * p1.z, -2.0f * p1.w);
        n2c2[c]  = pk2(act ? g_n2[ci] : 1e30f, 0.0f);
        if (tid == 0) {
            s_pidc[c] = act ? pid[ci] : -1;
            s_qc[c]   = act ? g_q[ci] : 0.0f;
        }
    }

    for (int h = tid; h < CPT * NB; h += RT) ((int*)s_hist)[h] = 0;
    if (tid < CPT) s_bcnt[tid] = 0;
    __syncthreads();

    const ulonglong2* xpj = (const ulonglong2*)g_xp;

    // ---- Pass A: count histogram of d2 (in-radius, self included) ----
    for (int j = tid; j < N; j += RT) {
        ulonglong2 a = xpj[2 * j + 0];
        ulonglong2 b = xpj[2 * j + 1];
        unsigned long long js[4] = {a.x, a.y, b.x, b.y};
        float n2j = g_n2[j];
        #pragma unroll
        for (int c = 0; c < CPT; c++) {
            float d2 = d2_f32x2(js, cs[c], n2c2[c], n2j);
            if (d2 <= 1.0f) {
                int bb = min((int)(fmaxf(d2, 0.0f) * (float)NB), NB - 1);
                atomicAdd(&s_hist[c][bb], 1);
            }
        }
    }
    __syncthreads();

    // ---- selection: boundary bin B and residual r per CP ----
    if (tid < CPT) {
        int cum = 0, B = NB, r = 0;
        for (int b = 0; b < NB; b++) {
            int nc = cum + s_hist[tid][b];
            if (nc >= KSEL2) { B = b; r = KSEL2 - cum; break; }
            cum = nc;
        }
        s_Bs[tid] = B; s_rs[tid] = r;
    }
    __syncthreads();

    int Breg[CPT];
    #pragma unroll
    for (int c = 0; c < CPT; c++) Breg[c] = s_Bs[c];

    // ---- Pass B: accumulate bins < B (lazy pid/q loads); gather boundary bin ----
    float acc[CPT];
    #pragma unroll
    for (int c = 0; c < CPT; c++) acc[c] = 0.0f;

    for (int j = tid; j < N; j += RT) {
        ulonglong2 a = xpj[2 * j + 0];
        ulonglong2 b = xpj[2 * j + 1];
        unsigned long long js[4] = {a.x, a.y, b.x, b.y};
        float n2j = g_n2[j];
        #pragma unroll
        for (int c = 0; c < CPT; c++) {
            float d2 = d2_f32x2(js, cs[c], n2c2[c], n2j);
            if (d2 <= 1.0f) {
                float d2c = fmaxf(d2, 0.0f);
                int bb = min((int)(d2c * (float)NB), NB - 1);
                int B = Breg[c];
                if (bb < B) {
                    if (pid[j] != s_pidc[c])
                        acc[c] += (1.0f - sqrtf(d2c)) * g_q[j];
                } else if (bb == B) {
                    float w = (pid[j] != s_pidc[c]) ? (1.0f - sqrtf(d2c)) * g_q[j] : 0.0f;
                    int p = atomicAdd(&s_bcnt[c], 1);
                    if (p < BCAP) { s_bk[c][p] = __float_as_uint(d2c); s_bw[c][p] = w; }
                }
            }
        }
    }
    __syncthreads();

    // ---- boundary mini-rank + per-CP reduction ----
    #pragma unroll
    for (int c = 0; c < CPT; c++) {
        float part = acc[c];
        int m = min(s_bcnt[c], BCAP);
        int r = s_rs[c];
        if (r > 0) {
            for (int e = tid; e < m; e += RT) {
                unsigned ke = s_bk[c][e];
                int rank = 0;
                for (int k = 0; k < m; k++) {
                    unsigned kk = s_bk[c][k];
                    rank += (kk < ke) || (kk == ke && k < e);
                }
                if (rank < r) part += s_bw[c][e];
            }
        }
        #pragma unroll
        for (int o = 16; o; o >>= 1) part += __shfl_down_sync(0xFFFFFFFFu, part, o);
        if ((tid & 31) == 0) s_red[tid >> 5] = part;
        __syncthreads();
        if (tid == 0) {
            float tot = 0.0f;
            #pragma unroll
            for (int w = 0; w < RT / 32; w++) tot += s_red[w];
            if (tot != 0.0f) atomicAdd(&g_rep, (double)(tot * s_qc[c]));
        }
        __syncthreads();
    }
}

__global__ void k_final(float* out, int N) {
    if (blockIdx.x == 0 && threadIdx.x == 0) {
        int mc = g_maskcnt;
        out[0] = (float)(mc > 0 ? g_att / (double)mc : 0.0);
        out[1] = (float)(g_rep / (double)N);
        out[2] = 0.0f;
        out[3] = 0.0f;
    }
}

extern "C" void kernel_launch(void* const* d_in, const int* in_sizes, int n_in,
                              void* d_out, int out_size) {
    const float* beta  = (const float*)d_in[0];
    const float* x     = (const float*)d_in[1];
    const int*   pid   = (const int*)d_in[2];
    const int*   recon = (const int*)d_in[3];
    const float* pt    = (const float*)d_in[4];
    const float* eta   = (const float*)d_in[5];
    float* out = (float*)d_out;
    int N = in_sizes[0];

    k_init<<<(NPIDMAX + 255) / 256, 256>>>();
    k_bestq<<<(N + 255) / 256, 256>>>(beta, pid, x, N);
    k_attract<<<(N + 127) / 128, 128>>>(x, pid, recon, pt, eta, N);
    k_repulse<<<NBLK, RT>>>(pid, N);
    k_final<<<1, 32>>>(out, N);
}

// round 9
// speedup vs baseline: 1.2407x; 1.2407x over previous
#include <cuda_runtime.h>
#include <math.h>

// Fixed-shape problem: N=16384, D=8, pid in [0,2000), K=128, R=1
#define NMAX    16384
#define NPIDMAX 2048
#define KSEL2   129     // top-(K+1) including self (self weight = 0)
#define CPT     4       // condensation points per repulsion block
#define RT      256     // threads per block
#define NB      256     // histogram bins over d2 in [0,1]
#define BCAP    128     // boundary-bin candidate capacity per CP

// -------- device scratch (small, allocation-free) --------
__device__ unsigned long long g_best[NPIDMAX];   // per-pid packed (beta_bits<<32 | ~idx)
__device__ float  g_q[NMAX];
__device__ float  g_n2[NMAX];
__device__ float4 g_xp[NMAX * 2];                // x packed as 2 float4 per node
__device__ int    g_cplist[NPIDMAX];
__device__ int    g_cpcount;
__device__ double g_att;
__device__ double g_rep;
__device__ int    g_maskcnt;

// predicated shared-memory histogram increment (no branch, no BSSY)
__device__ __forceinline__ void hist_add(unsigned smem_addr, unsigned pred) {
    asm volatile(
        "{\n\t"
        ".reg .pred p;\n\t"
        "setp.ne.u32 p, %1, 0;\n\t"
        "@p red.shared.add.u32 [%0], 1;\n\t"
        "}" :: "r"(smem_addr), "r"(pred) : "memory");
}

__global__ void k_init() {
    int i = blockIdx.x * blockDim.x + threadIdx.x;
    if (i < NPIDMAX) g_best[i] = 0ULL;
    if (i == 0) { g_cpcount = 0; g_att = 0.0; g_rep = 0.0; g_maskcnt = 0; }
}

// q = arctanh(beta)^2 + 0.01 ; |x|^2 ; pack x ; per-pid best
__global__ void k_bestq(const float* __restrict__ beta, const int* __restrict__ pid,
                        const float* __restrict__ x, int N) {
    int i = blockIdx.x * blockDim.x + threadIdx.x;
    if (i >= N) return;
    float b = beta[i];
    float t = atanhf(b);
    g_q[i] = t * t + 0.01f;
    float4 v0 = *(const float4*)(x + (size_t)i * 8);
    float4 v1 = *(const float4*)(x + (size_t)i * 8 + 4);
    float n2 = v0.x * v0.x + v0.y * v0.y + v0.z * v0.z + v0.w * v0.w
             + v1.x * v1.x + v1.y * v1.y + v1.z * v1.z + v1.w * v1.w;
    g_n2[i] = n2;
    g_xp[2 * i + 0] = v0;
    g_xp[2 * i + 1] = v1;
    int p = pid[i];
    if (p > 0 && p < NPIDMAX) {
        unsigned long long key =
            ((unsigned long long)__float_as_uint(b) << 32) |
            (unsigned long long)(0xFFFFFFFFu - (unsigned)i);
        atomicMax(&g_best[p], key);
    }
}

// compact (threads < NPIDMAX) + attraction, fused
__global__ void k_attract(const float* __restrict__ x, const int* __restrict__ pid,
                          const int* __restrict__ recon, const float* __restrict__ pt,
                          const float* __restrict__ eta, int N) {
    int i = blockIdx.x * blockDim.x + threadIdx.x;
    if (i > 0 && i < NPIDMAX) {
        unsigned long long key = g_best[i];
        if (key != 0ULL) {
            int idx = (int)(0xFFFFFFFFu - (unsigned)(key & 0xFFFFFFFFull));
            int pos = atomicAdd(&g_cpcount, 1);
            g_cplist[pos] = idx;
        }
    }
    float va = 0.0f; int m = 0;
    if (i < N) {
        int p = pid[i];
        if (p > 0 && pt[i] > 0.9f && recon[i] > 0 && fabsf(eta[i]) < 4.0f) {
            unsigned long long key = g_best[p];
            int a = (int)(0xFFFFFFFFu - (unsigned)(key & 0xFFFFFFFFull));
            const float4* xi = (const float4*)(x + (size_t)i * 8);
            const float4* xa = (const float4*)(x + (size_t)a * 8);
            float4 i0 = xi[0], i1 = xi[1], a0 = xa[0], a1 = xa[1];
            float d, d2 = 0.0f;
            d = i0.x - a0.x; d2 += d * d;
            d = i0.y - a0.y; d2 += d * d;
            d = i0.z - a0.z; d2 += d * d;
            d = i0.w - a0.w; d2 += d * d;
            d = i1.x - a1.x; d2 += d * d;
            d = i1.y - a1.y; d2 += d * d;
            d = i1.z - a1.z; d2 += d * d;
            d = i1.w - a1.w; d2 += d * d;
            va = d2 * g_q[i] * g_q[a];
            m = 1;
        }
    }
    #pragma unroll
    for (int o = 16; o; o >>= 1) {
        va += __shfl_down_sync(0xFFFFFFFFu, va, o);
        m  += __shfl_down_sync(0xFFFFFFFFu, m,  o);
    }
    if ((threadIdx.x & 31) == 0 && (m || va != 0.0f)) {
        atomicAdd(&g_att, (double)va);
        atomicAdd(&g_maskcnt, m);
    }
}

// ---- repulsion: branchless pass A histogram; predicated pass B accumulate ----
__global__ void __launch_bounds__(RT, 4) k_repulse(const int* __restrict__ pid, int N) {
    __shared__ int      s_hist[CPT][NB];
    __shared__ int      s_Bs[CPT];
    __shared__ int      s_rs[CPT];
    __shared__ int      s_bcnt[CPT];
    __shared__ unsigned s_bk[CPT][BCAP];
    __shared__ float    s_bw[CPT][BCAP];
    __shared__ float    s_qc[CPT];
    __shared__ float    s_red[RT / 32];

    int tid   = threadIdx.x;
    int ncp   = g_cpcount;
    int cbase = blockIdx.x * CPT;
    if (cbase >= ncp) return;

    // register-resident CP data: m2x = -2*xc, chain seeded with n2c
    float m2x[CPT][8], n2c[CPT];
    int   pidc[CPT];
    #pragma unroll
    for (int c = 0; c < CPT; c++) {
        int slot = cbase + c;
        bool act = slot < ncp;
        int ci = act ? g_cplist[slot] : 0;
        float4 p0 = g_xp[2 * ci + 0];
        float4 p1 = g_xp[2 * ci + 1];
        m2x[c][0] = -2.0f * p0.x; m2x[c][1] = -2.0f * p0.y;
        m2x[c][2] = -2.0f * p0.z; m2x[c][3] = -2.0f * p0.w;
        m2x[c][4] = -2.0f * p1.x; m2x[c][5] = -2.0f * p1.y;
        m2x[c][6] = -2.0f * p1.z; m2x[c][7] = -2.0f * p1.w;
        n2c[c]  = act ? g_n2[ci] : 1e30f;
        pidc[c] = act ? pid[ci]  : -1;
        if (tid == 0) s_qc[c] = act ? g_q[ci] : 0.0f;
    }

    for (int h = tid; h < CPT * NB; h += RT) ((int*)s_hist)[h] = 0;
    if (tid < CPT) s_bcnt[tid] = 0;
    __syncthreads();

    unsigned histbase[CPT];
    #pragma unroll
    for (int c = 0; c < CPT; c++)
        histbase[c] = (unsigned)__cvta_generic_to_shared(&s_hist[c][0]);

    // ---- Pass A: branchless count histogram ----
    for (int j = tid; j < N; j += RT) {
        float4 v0 = g_xp[2 * j + 0];
        float4 v1 = g_xp[2 * j + 1];
        float n2j = g_n2[j];
        #pragma unroll
        for (int c = 0; c < CPT; c++) {
            float d2 = fmaf(v0.x, m2x[c][0], n2c[c]);
            d2 = fmaf(v0.y, m2x[c][1], d2);
            d2 = fmaf(v0.z, m2x[c][2], d2);
            d2 = fmaf(v0.w, m2x[c][3], d2);
            d2 = fmaf(v1.x, m2x[c][4], d2);
            d2 = fmaf(v1.y, m2x[c][5], d2);
            d2 = fmaf(v1.z, m2x[c][6], d2);
            d2 = fmaf(v1.w, m2x[c][7], d2);
            d2 += n2j;
            float d2c = fmaxf(d2, 0.0f);
            int bb = min((int)(d2c * (float)NB), NB - 1);
            hist_add(histbase[c] + (unsigned)(bb << 2), (unsigned)(d2 <= 1.0f));
        }
    }
    __syncthreads();

    // ---- selection: boundary bin B and residual r per CP ----
    if (tid < CPT) {
        int cum = 0, B = NB, r = 0;
        for (int b = 0; b < NB; b++) {
            int nc = cum + s_hist[tid][b];
            if (nc >= KSEL2) { B = b; r = KSEL2 - cum; break; }
            cum = nc;
        }
        s_Bs[tid] = B; s_rs[tid] = r;
    }
    __syncthreads();

    int Breg[CPT];
    #pragma unroll
    for (int c = 0; c < CPT; c++) Breg[c] = s_Bs[c];

    // ---- Pass B: predicated accumulate (< B); rare boundary gather ----
    float acc[CPT];
    #pragma unroll
    for (int c = 0; c < CPT; c++) acc[c] = 0.0f;

    for (int j = tid; j < N; j += RT) {
        float4 v0 = g_xp[2 * j + 0];
        float4 v1 = g_xp[2 * j + 1];
        float n2j = g_n2[j];
        float qj  = g_q[j];
        int   pj  = pid[j];
        bool anyB = false;
        float d2s[CPT];
        #pragma unroll
        for (int c = 0; c < CPT; c++) {
            float d2 = fmaf(v0.x, m2x[c][0], n2c[c]);
            d2 = fmaf(v0.y, m2x[c][1], d2);
            d2 = fmaf(v0.z, m2x[c][2], d2);
            d2 = fmaf(v0.w, m2x[c][3], d2);
            d2 = fmaf(v1.x, m2x[c][4], d2);
            d2 = fmaf(v1.y, m2x[c][5], d2);
            d2 = fmaf(v1.z, m2x[c][6], d2);
            d2 = fmaf(v1.w, m2x[c][7], d2);
            d2 += n2j;
            d2s[c] = d2;
            float d2c = fmaxf(d2, 0.0f);
            int bb = min((int)(d2c * (float)NB), NB - 1);
            // predicated accumulate: sqrt always computed (MUFU), no branch
            float w = (1.0f - sqrtf(d2c)) * qj;
            bool sel = (d2 <= 1.0f) && (bb < Breg[c]) && (pj != pidc[c]);
            acc[c] += sel ? w : 0.0f;
            anyB |= (d2 <= 1.0f) && (bb == Breg[c]);
        }
        // rare: boundary-bin gather (warp-uniform guard)
        if (__any_sync(0xFFFFFFFFu, anyB)) {
            #pragma unroll
            for (int c = 0; c < CPT; c++) {
                float d2 = d2s[c];
                if (d2 <= 1.0f) {
                    float d2c = fmaxf(d2, 0.0f);
                    int bb = min((int)(d2c * (float)NB), NB - 1);
                    if (bb == Breg[c]) {
                        float w = (pj != pidc[c]) ? (1.0f - sqrtf(d2c)) * qj : 0.0f;
                        int p = atomicAdd(&s_bcnt[c], 1);
                        if (p < BCAP) { s_bk[c][p] = __float_as_uint(d2c); s_bw[c][p] = w; }
                    }
                }
            }
        }
    }
    __syncthreads();

    // ---- boundary mini-rank + per-CP reduction ----
    #pragma unroll
    for (int c = 0; c < CPT; c++) {
        float part = acc[c];
        int m = min(s_bcnt[c], BCAP);
        int r = s_rs[c];
        if (r > 0) {
            for (int e = tid; e < m; e += RT) {
                unsigned ke = s_bk[c][e];
                int rank = 0;
                for (int k = 0; k < m; k++) {
                    unsigned kk = s_bk[c][k];
                    rank += (kk < ke) || (kk == ke && k < e);
                }
                if (rank < r) part += s_bw[c][e];
            }
        }
        #pragma unroll
        for (int o = 16; o; o >>= 1) part += __shfl_down_sync(0xFFFFFFFFu, part, o);
        if ((tid & 31) == 0) s_red[tid >> 5] = part;
        __syncthreads();
        if (tid == 0) {
            float tot = 0.0f;
            #pragma unroll
            for (int w = 0; w < RT / 32; w++) tot += s_red[w];
            if (tot != 0.0f) atomicAdd(&g_rep, (double)(tot * s_qc[c]));
        }
        __syncthreads();
    }
}

__global__ void k_final(float* out, int N) {
    if (blockIdx.x == 0 && threadIdx.x == 0) {
        int mc = g_maskcnt;
        out[0] = (float)(mc > 0 ? g_att / (double)mc : 0.0);
        out[1] = (float)(g_rep / (double)N);
        out[2] = 0.0f;
        out[3] = 0.0f;
    }
}

extern "C" void kernel_launch(void* const* d_in, const int* in_sizes, int n_in,
                              void* d_out, int out_size) {
    const float* beta  = (const float*)d_in[0];
    const float* x     = (const float*)d_in[1];
    const int*   pid   = (const int*)d_in[2];
    const int*   recon = (const int*)d_in[3];
    const float* pt    = (const float*)d_in[4];
    const float* eta   = (const float*)d_in[5];
    float* out = (float*)d_out;
    int N = in_sizes[0];

    k_init<<<(NPIDMAX + 255) / 256, 256>>>();
    k_bestq<<<(N + 255) / 256, 256>>>(beta, pid, x, N);
    k_attract<<<(N + 127) / 128, 128>>>(x, pid, recon, pt, eta, N);
    int ngrp = (NPIDMAX + CPT - 1) / CPT;   // 512 blocks; ~500 active
    k_repulse<<<ngrp, RT>>>(pid, N);
    k_final<<<1, 32>>>(out, N);
}